// round 1
// baseline (speedup 1.0000x reference)
#include <cuda_runtime.h>

#define TT   65536
#define SD   100
#define HID  8
#define NOBS 12
#define DTC  0.01f

__device__ __forceinline__ unsigned long long pack2(float lo, float hi) {
    unsigned long long r;
    asm("mov.b64 %0, {%1, %2};" : "=l"(r) : "f"(lo), "f"(hi));
    return r;
}
__device__ __forceinline__ void unpack2(unsigned long long v, float& lo, float& hi) {
    asm("mov.b64 {%0, %1}, %2;" : "=f"(lo), "=f"(hi) : "l"(v));
}
__device__ __forceinline__ void fma2(unsigned long long& acc, unsigned long long a, unsigned long long b) {
    asm("fma.rn.f32x2 %0, %1, %2, %0;" : "+l"(acc) : "l"(a), "l"(b));
}
__device__ __forceinline__ void add2(unsigned long long& acc, unsigned long long b) {
    asm("add.rn.f32x2 %0, %0, %1;" : "+l"(acc) : "l"(b));
}

__global__ void __launch_bounds__(128, 1) greybox_kernel(
    const float* __restrict__ c0,
    const float* __restrict__ w,
    const float* __restrict__ u,
    const float* __restrict__ A,
    const float* __restrict__ Bw,
    const float* __restrict__ W1,
    const float* __restrict__ b1,
    const float* __restrict__ W2,
    const float* __restrict__ b2,
    const int*   __restrict__ obs,
    float* __restrict__ outc,
    float* __restrict__ outy)
{
    // ping-pong state buffers: g (100 + 4 zero pad), h (8)
    __shared__ __align__(16) float gbuf[2][104];
    __shared__ __align__(16) float hbuf[2][8];
    __shared__ __align__(16) float w2s[SD * HID];   // W2 staging for column access

    const int tid = threadIdx.x;
    const bool isA = (tid < SD);
    const bool isZ = (tid >= 104 && tid < 112);
    const int arow = tid;        // valid if isA
    const int zrow = tid - 104;  // valid if isZ

    // ---- one-time setup ----
    for (int i = tid; i < SD * HID; i += 128) w2s[i] = W2[i];
    if (tid < 104) { gbuf[0][tid] = 0.f; gbuf[1][tid] = 0.f; }
    if (tid < 8)   { hbuf[0][tid] = 0.f; hbuf[1][tid] = 0.f; }
    __syncthreads();

    // per-lane row of [A ; W1], packed f32x2 (52 pairs incl. zero pad)
    unsigned long long rva[52];
#pragma unroll
    for (int k = 0; k < 52; k++) rva[k] = 0ull;
    unsigned long long mrow[4] = {0ull, 0ull, 0ull, 0ull};  // dt*(A@W2) row (or dt*(W1@W2))
    unsigned long long w2d[4]  = {0ull, 0ull, 0ull, 0ull};  // dt*W2 row (A lanes, for c output)
    float bw0 = 0.f, bw1 = 0.f, cb = 0.f, gc = 0.f;
    unsigned int ymask = 0u;

    if (isA) {
        const float* Ar = A + arow * SD;
#pragma unroll
        for (int k = 0; k < 50; k++) rva[k] = pack2(Ar[2 * k], Ar[2 * k + 1]);
        float m[8]; float s = 0.f;
#pragma unroll
        for (int j = 0; j < 8; j++) m[j] = 0.f;
        for (int k = 0; k < SD; k++) {
            float a = Ar[k];
#pragma unroll
            for (int j = 0; j < 8; j++) m[j] += a * w2s[k * HID + j];
            s += a * b2[k];
        }
#pragma unroll
        for (int j = 0; j < 4; j++) mrow[j] = pack2(DTC * m[2 * j], DTC * m[2 * j + 1]);
        gc = DTC * s;
#pragma unroll
        for (int j = 0; j < 4; j++)
            w2d[j] = pack2(DTC * w2s[arow * HID + 2 * j], DTC * w2s[arow * HID + 2 * j + 1]);
        cb  = DTC * b2[arow];
        bw0 = Bw[arow * 2];
        bw1 = Bw[arow * 2 + 1];
#pragma unroll
        for (int q = 0; q < NOBS; q++) if (obs[q] == arow) ymask |= (1u << q);
    } else if (isZ) {
        const float* Wr = W1 + zrow * SD;
#pragma unroll
        for (int k = 0; k < 50; k++) rva[k] = pack2(Wr[2 * k], Wr[2 * k + 1]);
        float m[8]; float s = 0.f;
#pragma unroll
        for (int j = 0; j < 8; j++) m[j] = 0.f;
        for (int k = 0; k < SD; k++) {
            float a = Wr[k];
#pragma unroll
            for (int j = 0; j < 8; j++) m[j] += a * w2s[k * HID + j];
            s += a * b2[k];
        }
#pragma unroll
        for (int j = 0; j < 4; j++) mrow[j] = pack2(DTC * m[2 * j], DTC * m[2 * j + 1]);
        gc = b1[zrow] + DTC * s;   // zc
    }

    // initial state: h_0 = 0, g_0 = c0 - dt*b2  (so that c_0 = g_0 + dt*(W2 h_0 + b2) = c0)
    float g_own = 0.f;
    if (isA) {
        float g0 = c0[arow] - DTC * b2[arow];
        gbuf[0][arow] = g0;
        g_own = g0;
    }
    __syncthreads();

    // prefetch inputs for iteration 0 (produces state t=1 from u[0], w[0..1])
    float u_cur = 0.f;
    if (isA) u_cur = u[arow];
    float w0_cur = w[0], w1_cur = w[1];

    int p = 0;
    for (int k = 0; k < TT; k++) {
        // prefetch next iteration's inputs (hide L2 latency under the dot)
        int kn = (k + 1 < TT) ? (k + 1) : k;
        float u_nxt = 0.f;
        if (isA) u_nxt = __ldcg(&u[(size_t)kn * SD + arow]);
        float w0_nxt = __ldcg(&w[kn * 2]);
        float w1_nxt = __ldcg(&w[kn * 2 + 1]);

        const unsigned long long* hp = reinterpret_cast<const unsigned long long*>(hbuf[p]);
        unsigned long long h0 = hp[0], h1 = hp[1], h2 = hp[2], h3 = hp[3];

        // ---- emit c_k, y_k (state index k, valid for k >= 1) ----
        if (k > 0) {
            if (isA) {
                unsigned long long cacc = 0ull;
                fma2(cacc, w2d[0], h0); fma2(cacc, w2d[1], h1);
                fma2(cacc, w2d[2], h2); fma2(cacc, w2d[3], h3);
                float lo, hi; unpack2(cacc, lo, hi);
                float cv = g_own + cb + lo + hi;
                outc[(size_t)(k - 1) * SD + arow] = cv;
                if (ymask) {
#pragma unroll
                    for (int q = 0; q < NOBS; q++)
                        if (ymask & (1u << q)) outy[(size_t)(k - 1) * NOBS + q] = cv;
                }
            }
        }

        // ---- advance: dot of row against g_k, plus M·h_k ----
        unsigned long long a0 = 0ull, a1 = 0ull, a2 = 0ull, a3 = 0ull;
        const ulonglong2* gp2 = reinterpret_cast<const ulonglong2*>(gbuf[p]);
#pragma unroll
        for (int q = 0; q < 26; q++) {
            ulonglong2 gg = gp2[q];
            if (q & 1) { fma2(a2, rva[2 * q], gg.x); fma2(a3, rva[2 * q + 1], gg.y); }
            else       { fma2(a0, rva[2 * q], gg.x); fma2(a1, rva[2 * q + 1], gg.y); }
        }
        fma2(a0, mrow[0], h0); fma2(a1, mrow[1], h1);
        fma2(a2, mrow[2], h2); fma2(a3, mrow[3], h3);
        add2(a0, a1); add2(a2, a3); add2(a0, a2);
        float lo, hi; unpack2(a0, lo, hi);
        float dot = lo + hi;

        if (isA) {
            float gn = dot + gc + bw0 * w0_cur + bw1 * w1_cur + u_cur;
            gbuf[p ^ 1][arow] = gn;
            g_own = gn;
        } else if (isZ) {
            float hn = tanhf(dot + gc);
            hbuf[p ^ 1][zrow] = hn;
        }

        u_cur = u_nxt; w0_cur = w0_nxt; w1_cur = w1_nxt;
        __syncthreads();
        p ^= 1;
    }

    // ---- epilogue: emit c_T, y_T ----
    if (isA) {
        const unsigned long long* hp = reinterpret_cast<const unsigned long long*>(hbuf[p]);
        unsigned long long cacc = 0ull;
        fma2(cacc, w2d[0], hp[0]); fma2(cacc, w2d[1], hp[1]);
        fma2(cacc, w2d[2], hp[2]); fma2(cacc, w2d[3], hp[3]);
        float lo, hi; unpack2(cacc, lo, hi);
        float cv = g_own + cb + lo + hi;
        outc[(size_t)(TT - 1) * SD + arow] = cv;
        if (ymask) {
#pragma unroll
            for (int q = 0; q < NOBS; q++)
                if (ymask & (1u << q)) outy[(size_t)(TT - 1) * NOBS + q] = cv;
        }
    }
}

extern "C" void kernel_launch(void* const* d_in, const int* in_sizes, int n_in,
                              void* d_out, int out_size) {
    const float* c0  = (const float*)d_in[0];
    const float* w   = (const float*)d_in[1];
    const float* u   = (const float*)d_in[2];
    const float* A   = (const float*)d_in[3];
    const float* Bw  = (const float*)d_in[4];
    const float* W1  = (const float*)d_in[5];
    const float* b1  = (const float*)d_in[6];
    const float* W2  = (const float*)d_in[7];
    const float* b2  = (const float*)d_in[8];
    const int*   ob  = (const int*)d_in[9];

    float* outc = (float*)d_out;                      // (T, 100)
    float* outy = (float*)d_out + (size_t)TT * SD;    // (T, 12)

    greybox_kernel<<<1, 128>>>(c0, w, u, A, Bw, W1, b1, W2, b2, ob, outc, outy);
}